// round 4
// baseline (speedup 1.0000x reference)
#include <cuda_runtime.h>
#include <math.h>

// Problem constants (from reference): B=1024 batches, NL=64 layers, W=2048 wavelengths.
// Inner scan runs over layers 1..NL-2 inclusive = 62 layers.
#define TMM_B  1024
#define TMM_NL 64
#define TMM_W  2048
#define TMM_NI 62           // inner layers
#define TWO_PI 6.283185307179586f
#define EPS_N  1e-8f
#define EPS_Y  1e-9f

// Structure exploit: n is real, so every layer matrix is
//   [[c, i*(-s/(n+eps))], [i*(-n*s), c]]
// i.e. real diagonal, purely imaginary off-diagonal. That form is closed under
// multiplication, so the whole 2x2 complex scan reduces to 4 real scalars:
//   A = Re(M00), Bv = Im(M01), C = Im(M10), D = Re(M11)
// with recurrence (M_new = M * M_layer):
//   A' = A*c + Bv*(n*s)        Bv' = Bv*c - A*(s/(n+eps))
//   C' = C*c - D *(n*s)        D'  = D*c  + C*(s/(n+eps))

__global__ __launch_bounds__(256)
void tmm_kernel(const float* __restrict__ n_layers,
                const float* __restrict__ d_layers,
                const float* __restrict__ wavelengths,
                float* __restrict__ out)
{
    __shared__ float s_nd [TMM_NI];   // n_i * d_i
    __shared__ float s_n  [TMM_NI];   // n_i
    __shared__ float s_inv[TMM_NI];   // 1 / (n_i + EPS_N)
    __shared__ float s_end[2];        // n_in, n_sub

    const int b = blockIdx.y;
    const int w = blockIdx.x * blockDim.x + threadIdx.x;

    const float* nrow = n_layers + (size_t)b * TMM_NL;
    const float* drow = d_layers + (size_t)b * TMM_NL;

    // Stage per-batch layer constants into shared memory (62*3 floats).
    for (int i = threadIdx.x; i < TMM_NI; i += blockDim.x) {
        float ni = nrow[i + 1];
        float di = drow[i + 1];
        s_nd [i] = ni * di;
        s_n  [i] = ni;
        s_inv[i] = 1.0f / (ni + EPS_N);
    }
    if (threadIdx.x == 0) {
        s_end[0] = nrow[0];
        s_end[1] = nrow[TMM_NL - 1];
    }
    __syncthreads();

    const float k0 = TWO_PI / wavelengths[w];

    float A  = 1.0f;
    float Bv = 0.0f;
    float C  = 0.0f;
    float D  = 1.0f;

    #pragma unroll 2
    for (int i = 0; i < TMM_NI; i++) {
        float s, c;
        sincosf(s_nd[i] * k0, &s, &c);     // precise path this round
        const float ns   = s_n[i]   * s;   // n*s
        const float sinv = s_inv[i] * s;   // s/(n+eps)

        const float A2 = fmaf(Bv,  ns,   A  * c);
        const float B2 = fmaf(-A,  sinv, Bv * c);
        const float C2 = fmaf(-D,  ns,   C  * c);
        const float D2 = fmaf(C,   sinv, D  * c);
        A = A2; Bv = B2; C = C2; D = D2;
    }

    // E = A + i*Bv*n_sub ; H = D*n_sub + i*C ; Y = H/(E+EPS_Y)
    // r = (n_in - Y)/(n_in + Y) = (n_in*(E+eps) - H) / (n_in*(E+eps) + H)
    const float nin  = s_end[0];
    const float nsub = s_end[1];
    const float Ae   = A + EPS_Y;

    const float t1 = nin * Ae;          // Re(n_in*(E+eps))
    const float t2 = D * nsub;          // Re(H)
    const float t3 = nin * Bv * nsub;   // Im(n_in*(E+eps))
    // Im(H) = C

    const float nr = t1 - t2;
    const float ni = t3 - C;
    const float dr = t1 + t2;
    const float di = t3 + C;

    const float R = fmaf(nr, nr, ni * ni) / fmaf(dr, dr, di * di);

    out[(size_t)b * TMM_W + w] = R;
}

extern "C" void kernel_launch(void* const* d_in, const int* in_sizes, int n_in,
                              void* d_out, int out_size)
{
    const float* n_layers    = (const float*)d_in[0];   // [B, NL]
    const float* d_layers    = (const float*)d_in[1];   // [B, NL]
    const float* wavelengths = (const float*)d_in[2];   // [W]
    float* out = (float*)d_out;                         // [B, W]

    dim3 block(256);
    dim3 grid(TMM_W / 256, TMM_B);
    tmm_kernel<<<grid, block>>>(n_layers, d_layers, wavelengths, out);
}

// round 5
// speedup vs baseline: 2.1950x; 2.1950x over previous
#include <cuda_runtime.h>
#include <math.h>

// Problem constants: B=1024 batches, NL=64 layers, W=2048 wavelengths.
// Inner scan: layers 1..NL-2 inclusive = 62 layers.
#define TMM_B  1024
#define TMM_NL 64
#define TMM_W  2048
#define TMM_NI 62
#define TWO_PI 6.283185307179586f
#define EPS_N  1e-8f
#define EPS_Y  1e-9f

// Real-n structure: every layer matrix has real diagonal, purely imaginary
// off-diagonal; closed under multiplication -> 4 real scalar recurrence:
//   A' = A*c + Bv*(n*s)   Bv' = Bv*c - A*(s/(n+eps))
//   C' = C*c - D *(n*s)   D'  = D*c  + C*(s/(n+eps))
// R4 change: __sincosf (MUFU fast path) replaces precise sincosf; the
// ~2400x rel-err headroom (4.1e-7 measured vs 1e-3 gate) absorbs the
// fast-path error compounded over 62 layers (predicted ~1e-5..1e-4).

__global__ __launch_bounds__(256)
void tmm_kernel(const float* __restrict__ n_layers,
                const float* __restrict__ d_layers,
                const float* __restrict__ wavelengths,
                float* __restrict__ out)
{
    __shared__ float s_nd [TMM_NI];   // n_i * d_i
    __shared__ float s_n  [TMM_NI];   // n_i
    __shared__ float s_inv[TMM_NI];   // 1 / (n_i + EPS_N)
    __shared__ float s_end[2];        // n_in, n_sub

    const int b = blockIdx.y;
    const int w = blockIdx.x * blockDim.x + threadIdx.x;

    const float* nrow = n_layers + (size_t)b * TMM_NL;
    const float* drow = d_layers + (size_t)b * TMM_NL;

    for (int i = threadIdx.x; i < TMM_NI; i += blockDim.x) {
        float ni = nrow[i + 1];
        float di = drow[i + 1];
        s_nd [i] = ni * di;
        s_n  [i] = ni;
        s_inv[i] = 1.0f / (ni + EPS_N);
    }
    if (threadIdx.x == 0) {
        s_end[0] = nrow[0];
        s_end[1] = nrow[TMM_NL - 1];
    }
    __syncthreads();

    const float k0 = TWO_PI / wavelengths[w];

    float A  = 1.0f;
    float Bv = 0.0f;
    float C  = 0.0f;
    float D  = 1.0f;

    // Unroll 4: the __sincosf of layer i+1..i+3 is independent of the serial
    // recurrence, letting ptxas hoist MUFU issues ahead (lat=16) of the FMA chain.
    #pragma unroll 4
    for (int i = 0; i < TMM_NI; i++) {
        float s, c;
        __sincosf(s_nd[i] * k0, &s, &c);   // MUFU fast path
        const float ns   = s_n[i]   * s;   // n*s
        const float sinv = s_inv[i] * s;   // s/(n+eps)

        const float A2 = fmaf(Bv,  ns,   A  * c);
        const float B2 = fmaf(-A,  sinv, Bv * c);
        const float C2 = fmaf(-D,  ns,   C  * c);
        const float D2 = fmaf(C,   sinv, D  * c);
        A = A2; Bv = B2; C = C2; D = D2;
    }

    // E = A + i*Bv*n_sub ; H = D*n_sub + i*C ; Y = H/(E+EPS_Y)
    // r = (n_in*(E+eps) - H) / (n_in*(E+eps) + H) ; R = |r|^2
    const float nin  = s_end[0];
    const float nsub = s_end[1];
    const float Ae   = A + EPS_Y;

    const float t1 = nin * Ae;
    const float t2 = D * nsub;
    const float t3 = nin * Bv * nsub;

    const float nr = t1 - t2;
    const float ni = t3 - C;
    const float dr = t1 + t2;
    const float di = t3 + C;

    const float R = fmaf(nr, nr, ni * ni) / fmaf(dr, dr, di * di);

    out[(size_t)b * TMM_W + w] = R;
}

extern "C" void kernel_launch(void* const* d_in, const int* in_sizes, int n_in,
                              void* d_out, int out_size)
{
    const float* n_layers    = (const float*)d_in[0];
    const float* d_layers    = (const float*)d_in[1];
    const float* wavelengths = (const float*)d_in[2];
    float* out = (float*)d_out;

    dim3 block(256);
    dim3 grid(TMM_W / 256, TMM_B);
    tmm_kernel<<<grid, block>>>(n_layers, d_layers, wavelengths, out);
}

// round 6
// speedup vs baseline: 2.5044x; 1.1410x over previous
#include <cuda_runtime.h>
#include <math.h>

// B=1024, NL=64, W=2048; inner scan = 62 layers.
#define TMM_B  1024
#define TMM_NL 64
#define TMM_W  2048
#define TMM_NI 62
#define TWO_PI 6.283185307179586f
#define EPS_N  1e-8f
#define EPS_Y  1e-9f

// R5: pack the 4-real-scalar recurrence into two f32x2 lanes.
//   P = (A, C), Q = (Bv, D)
//   P' = P*(c,c) + Q*(n*s, -n*s)
//   Q' = Q*(c,c) + P*(-s/(n+e), +s/(n+e))
// FFMA2 (fma.rn.f32x2) halves FMA-pipe issues; per-layer cost drops from the
// measured ~22 cyc/SMSP to the SFU floor of 16 cyc (2 MUFU @ rt 8).

typedef unsigned long long u64;

__device__ __forceinline__ u64 pk2(float lo, float hi) {
    u64 r; asm("mov.b64 %0, {%1, %2};" : "=l"(r) : "f"(lo), "f"(hi)); return r;
}
__device__ __forceinline__ void upk2(u64 v, float& lo, float& hi) {
    asm("mov.b64 {%0, %1}, %2;" : "=f"(lo), "=f"(hi) : "l"(v));
}
__device__ __forceinline__ u64 mul2(u64 a, u64 b) {
    u64 r; asm("mul.rn.f32x2 %0, %1, %2;" : "=l"(r) : "l"(a), "l"(b)); return r;
}
__device__ __forceinline__ u64 fma2(u64 a, u64 b, u64 c) {
    u64 r; asm("fma.rn.f32x2 %0, %1, %2, %3;" : "=l"(r) : "l"(a), "l"(b), "l"(c)); return r;
}

__global__ __launch_bounds__(256)
void tmm_kernel(const float* __restrict__ n_layers,
                const float* __restrict__ d_layers,
                const float* __restrict__ wavelengths,
                float* __restrict__ out)
{
    __shared__ float  s_nd[TMM_NI];     // n_i * d_i
    __shared__ float4 s_q [TMM_NI];     // {n, -n, -1/(n+e), +1/(n+e)}
    __shared__ float  s_end[2];         // n_in, n_sub

    const int b = blockIdx.y;
    const int w = blockIdx.x * blockDim.x + threadIdx.x;

    const float* nrow = n_layers + (size_t)b * TMM_NL;
    const float* drow = d_layers + (size_t)b * TMM_NL;

    for (int i = threadIdx.x; i < TMM_NI; i += blockDim.x) {
        float ni  = nrow[i + 1];
        float di  = drow[i + 1];
        float inv = 1.0f / (ni + EPS_N);
        s_nd[i] = ni * di;
        s_q [i] = make_float4(ni, -ni, -inv, inv);
    }
    if (threadIdx.x == 0) {
        s_end[0] = nrow[0];
        s_end[1] = nrow[TMM_NL - 1];
    }
    __syncthreads();

    const float k0 = TWO_PI / wavelengths[w];

    u64 P = pk2(1.0f, 0.0f);   // (A, C)
    u64 Q = pk2(0.0f, 1.0f);   // (Bv, D)

    #pragma unroll 4
    for (int i = 0; i < TMM_NI; i++) {
        float s, c;
        __sincosf(s_nd[i] * k0, &s, &c);

        const float4 q = s_q[i];            // one LDS.128
        const u64 ss  = pk2(s, s);
        const u64 cc  = pk2(c, c);
        const u64 nmn = pk2(q.x, q.y);      // (n, -n)    — adjacent regs, MOV elides
        const u64 miv = pk2(q.z, q.w);      // (-inv, inv)

        const u64 u  = mul2(ss, nmn);       // (n*s, -n*s)
        const u64 v  = mul2(ss, miv);       // (-sinv, +sinv)
        const u64 t1 = mul2(Q, u);
        const u64 t2 = mul2(P, v);
        P = fma2(P, cc, t1);
        Q = fma2(Q, cc, t2);
    }

    float A, C, Bv, D;
    upk2(P, A, C);
    upk2(Q, Bv, D);

    // E = A + i*Bv*n_sub ; H = D*n_sub + i*C
    // r = (n_in*(E+eps) - H) / (n_in*(E+eps) + H) ; R = |r|^2
    const float nin  = s_end[0];
    const float nsub = s_end[1];
    const float Ae   = A + EPS_Y;

    const float t1 = nin * Ae;
    const float t2 = D * nsub;
    const float t3 = nin * Bv * nsub;

    const float nr = t1 - t2;
    const float ni = t3 - C;
    const float dr = t1 + t2;
    const float di = t3 + C;

    const float R = fmaf(nr, nr, ni * ni) / fmaf(dr, dr, di * di);

    out[(size_t)b * TMM_W + w] = R;
}

extern "C" void kernel_launch(void* const* d_in, const int* in_sizes, int n_in,
                              void* d_out, int out_size)
{
    const float* n_layers    = (const float*)d_in[0];
    const float* d_layers    = (const float*)d_in[1];
    const float* wavelengths = (const float*)d_in[2];
    float* out = (float*)d_out;

    dim3 block(256);
    dim3 grid(TMM_W / 256, TMM_B);
    tmm_kernel<<<grid, block>>>(n_layers, d_layers, wavelengths, out);
}